// round 11
// baseline (speedup 1.0000x reference)
#include <cuda_runtime.h>
#include <cuda_bf16.h>
#include <cstdint>

#define BB 4
#define HH 8
#define LQ 512
#define NBLK 32
#define NTOK 128
#define DH 64
#define MT 64
#define THREADS 128

#define OUT_ELEMS  (BB * LQ * HH * DH)
#define ATTN_ELEMS ((size_t)BB * HH * LQ * NBLK * NTOK)

#define QSTR 72           // bf16 elements per row (64 + 8 pad)
#define RB (QSTR * 2)     // 144 bytes per row

// smem byte offsets
#define OFF_QH 0
#define OFF_QL (OFF_QH + 64 * RB)    // 9216 each (Q is 64 rows)
#define OFF_KH (OFF_QL + 64 * RB)
#define OFF_KL (OFF_KH + 128 * RB)   // 18432 each
#define OFF_VH (OFF_KL + 128 * RB)
#define OFF_VL (OFF_VH + 128 * RB)
#define SMEM_BYTES (OFF_VL + 128 * RB)  // 92160

typedef unsigned long long ull;

__device__ __forceinline__ uint32_t s2u(const void* p) {
    uint32_t a;
    asm("{ .reg .u64 t; cvta.to.shared.u64 t, %1; cvt.u32.u64 %0, t; }" : "=r"(a) : "l"(p));
    return a;
}
__device__ __forceinline__ ull pack2(float x, float y) {
    ull r; asm("mov.b64 %0, {%1,%2};" : "=l"(r) : "f"(x), "f"(y)); return r;
}
__device__ __forceinline__ void unpack2(ull v, float& x, float& y) {
    asm("mov.b64 {%0,%1}, %2;" : "=f"(x), "=f"(y) : "l"(v));
}
__device__ __forceinline__ ull add2(ull a, ull b) {
    ull d; asm("add.rn.f32x2 %0, %1, %2;" : "=l"(d) : "l"(a), "l"(b)); return d;
}
__device__ __forceinline__ ull mul2(ull a, ull b) {
    ull d; asm("mul.rn.f32x2 %0, %1, %2;" : "=l"(d) : "l"(a), "l"(b)); return d;
}
__device__ __forceinline__ ull fma2(ull a, ull b, ull c) {
    ull d; asm("fma.rn.f32x2 %0, %1, %2, %3;" : "=l"(d) : "l"(a), "l"(b), "l"(c)); return d;
}
__device__ __forceinline__ void ldsm4(uint32_t* r, uint32_t a) {
    asm volatile("ldmatrix.sync.aligned.m8n8.x4.shared.b16 {%0,%1,%2,%3}, [%4];"
                 : "=r"(r[0]), "=r"(r[1]), "=r"(r[2]), "=r"(r[3]) : "r"(a));
}
__device__ __forceinline__ void ldsm4t(uint32_t* r, uint32_t a) {
    asm volatile("ldmatrix.sync.aligned.m8n8.x4.trans.shared.b16 {%0,%1,%2,%3}, [%4];"
                 : "=r"(r[0]), "=r"(r[1]), "=r"(r[2]), "=r"(r[3]) : "r"(a));
}
__device__ __forceinline__ void mma16816(float* c, const uint32_t* a, const uint32_t* b) {
    asm volatile(
        "mma.sync.aligned.m16n8k16.row.col.f32.bf16.bf16.f32 "
        "{%0,%1,%2,%3}, {%4,%5,%6,%7}, {%8,%9}, {%0,%1,%2,%3};"
        : "+f"(c[0]), "+f"(c[1]), "+f"(c[2]), "+f"(c[3])
        : "r"(a[0]), "r"(a[1]), "r"(a[2]), "r"(a[3]), "r"(b[0]), "r"(b[1]));
}

// split one fp32 float4 into bf16 hi/lo, store 8B each
__device__ __forceinline__ void split_store(float4 v, char* base_hi, char* base_lo) {
    __nv_bfloat162 h0 = __floats2bfloat162_rn(v.x, v.y);
    __nv_bfloat162 h1 = __floats2bfloat162_rn(v.z, v.w);
    float lx = v.x - __bfloat162float(h0.x);
    float ly = v.y - __bfloat162float(h0.y);
    float lz = v.z - __bfloat162float(h1.x);
    float lw = v.w - __bfloat162float(h1.y);
    __nv_bfloat162 e0 = __floats2bfloat162_rn(lx, ly);
    __nv_bfloat162 e1 = __floats2bfloat162_rn(lz, lw);
    uint2 hh; hh.x = *(uint32_t*)&h0; hh.y = *(uint32_t*)&h1;
    uint2 ll; ll.x = *(uint32_t*)&e0; ll.y = *(uint32_t*)&e1;
    *(uint2*)base_hi = hh;
    *(uint2*)base_lo = ll;
}

__global__ __launch_bounds__(THREADS, 2)
void attn_mma_kernel(const float* __restrict__ qg, const float* __restrict__ kg,
                     const float* __restrict__ vg, const float* __restrict__ ag,
                     float* __restrict__ out, float* __restrict__ attnw, int write_attn) {
    extern __shared__ __align__(16) char sm[];
    const uint32_t sb = s2u(sm);
    const int tid = threadIdx.x, lane = tid & 31, wid = tid >> 5;  // 4 warps
    const int g = lane >> 2, qd = lane & 3;
    const int bx = blockIdx.x;
    const int qt = bx & 7, hd = (bx >> 3) & 7, b = bx >> 6;
    const int l0 = qt * MT;

    const size_t kvstride = (size_t)HH * NTOK * DH;
    const size_t kvoff0 = ((size_t)(b * NBLK) * HH + hd) * (NTOK * DH);

    // ---- Q load + split (scale = 1/8 * log2e folded) ----
    {
        const float SC = 0.125f * 1.4426950408889634f;
        const float4* qg4 = (const float4*)(qg + (size_t)((b * HH + hd) * LQ + l0) * DH);
#pragma unroll
        for (int i = 0; i < 8; i++) {
            int idx = tid + i * THREADS;
            int row = idx >> 4, c4 = idx & 15;
            float4 v = qg4[idx];
            v.x *= SC; v.y *= SC; v.z *= SC; v.w *= SC;
            char* base = sm + row * RB + c4 * 8;
            split_store(v, base + OFF_QH, base + OFF_QL);
        }
    }

    // ldmatrix base addresses
    const uint32_t aQ = sb + OFF_QH + (uint32_t)((wid * 16 + (lane & 15)) * RB + (lane >> 4) * 16);
    const uint32_t bK = sb + OFF_KH +
        (uint32_t)((((lane >> 4) & 1) * 8 + (lane & 7)) * RB + ((lane >> 3) & 1) * 16);
    const uint32_t bV = sb + OFF_VH + (uint32_t)((lane & 15) * RB + ((lane >> 4) & 1) * 16);

    const float* asrow = ag + (size_t)((b * HH + hd) * LQ + l0 + wid * 16 + g) * NBLK;
    float* awbase = attnw + (size_t)((b * HH + hd) * LQ + l0 + wid * 16 + g) * (NBLK * NTOK)
                    + 2 * qd;

    float acc2[8][4];  // out accumulators m16 x d64
#pragma unroll
    for (int ni = 0; ni < 8; ni++)
#pragma unroll
        for (int j = 0; j < 4; j++) acc2[ni][j] = 0.f;

    // exp2 constants
    const ull MAGIC2 = 0x4B4000004B400000ULL;
    const ull NMAGIC2 = 0xCB400000CB400000ULL;
    const ull NEG1_2 = 0xBF800000BF800000ULL;
    const ull ONE2 = 0x3F8000003F800000ULL;
    const ull C5 = pack2(0.0013333558f, 0.0013333558f);
    const ull C4 = pack2(0.0096181291f, 0.0096181291f);
    const ull C3 = pack2(0.0555041087f, 0.0555041087f);
    const ull C2 = pack2(0.2402265070f, 0.2402265070f);
    const ull C1 = pack2(0.6931471806f, 0.6931471806f);

    for (int nb = 0; nb < NBLK; nb++) {
        __syncthreads();  // GEMM2(nb-1) done with K/V tiles
        // ---- load + split K,V (batches of 8 float4 for MLP) ----
        {
            const float4* kg4 = (const float4*)(kg + kvoff0 + (size_t)nb * kvstride);
            const float4* vg4 = (const float4*)(vg + kvoff0 + (size_t)nb * kvstride);
#pragma unroll
            for (int c = 0; c < 2; c++) {
                float4 buf[8];
#pragma unroll
                for (int j = 0; j < 8; j++) buf[j] = kg4[tid + (c * 8 + j) * THREADS];
#pragma unroll
                for (int j = 0; j < 8; j++) {
                    int idx = tid + (c * 8 + j) * THREADS;
                    int row = idx >> 4, c4 = idx & 15;
                    char* base = sm + row * RB + c4 * 8;
                    split_store(buf[j], base + OFF_KH, base + OFF_KL);
                }
            }
#pragma unroll
            for (int c = 0; c < 2; c++) {
                float4 buf[8];
#pragma unroll
                for (int j = 0; j < 8; j++) buf[j] = vg4[tid + (c * 8 + j) * THREADS];
#pragma unroll
                for (int j = 0; j < 8; j++) {
                    int idx = tid + (c * 8 + j) * THREADS;
                    int row = idx >> 4, c4 = idx & 15;
                    char* base = sm + row * RB + c4 * 8;
                    split_store(buf[j], base + OFF_VH, base + OFF_VL);
                }
            }
        }
        __syncthreads();  // tiles ready

        // ---- GEMM1: S(m16 x t128) = Q @ K^T, 3 bf16 products ----
        float acc[16][4];
#pragma unroll
        for (int ni = 0; ni < 16; ni++)
#pragma unroll
            for (int j = 0; j < 4; j++) acc[ni][j] = 0.f;

#pragma unroll
        for (int ks = 0; ks < 4; ks++) {
            uint32_t Ah[4], Al[4];
            ldsm4(Ah, aQ + ks * 32);
            ldsm4(Al, aQ + (OFF_QL - OFF_QH) + ks * 32);
#pragma unroll
            for (int np = 0; np < 8; np++) {
                uint32_t bh[4], bl[4];
                ldsm4(bh, bK + np * (16 * RB) + ks * 32);
                ldsm4(bl, bK + (OFF_KL - OFF_KH) + np * (16 * RB) + ks * 32);
                mma16816(acc[2 * np], Ah, bh);
                mma16816(acc[2 * np], Ah, bl);
                mma16816(acc[2 * np], Al, bh);
                mma16816(acc[2 * np + 1], Ah, bh + 2);
                mma16816(acc[2 * np + 1], Ah, bl + 2);
                mma16816(acc[2 * np + 1], Al, bh + 2);
            }
        }

        // ---- softmax: e = 2^S, full-row sums within warp (quad shuffle) ----
        ull s2a = 0ULL, s2b = 0ULL;
#pragma unroll
        for (int ni = 0; ni < 16; ni++) {
#pragma unroll
            for (int h2 = 0; h2 < 2; h2++) {
                ull y2 = pack2(acc[ni][2 * h2], acc[ni][2 * h2 + 1]);
                ull t2 = add2(y2, MAGIC2);
                ull u2 = add2(t2, NMAGIC2);
                ull f2 = fma2(u2, NEG1_2, y2);
                ull p2 = fma2(C5, f2, C4);
                p2 = fma2(p2, f2, C3);
                p2 = fma2(p2, f2, C2);
                p2 = fma2(p2, f2, C1);
                p2 = fma2(p2, f2, ONE2);
                uint32_t tlo = (uint32_t)t2, thi = (uint32_t)(t2 >> 32);
                uint32_t plo = (uint32_t)p2, phi = (uint32_t)(p2 >> 32);
                float e0 = __int_as_float(plo + (tlo << 23));
                float e1 = __int_as_float(phi + (thi << 23));
                acc[ni][2 * h2] = e0;
                acc[ni][2 * h2 + 1] = e1;
                if (h2 == 0) s2a = add2(s2a, pack2(e0, e1));
                else         s2b = add2(s2b, pack2(e0, e1));
            }
        }
        float sa0, sa1, sb0, sb1;
        unpack2(s2a, sa0, sa1);
        unpack2(s2b, sb0, sb1);
        float suma = sa0 + sa1, sumb = sb0 + sb1;
        suma += __shfl_xor_sync(0xffffffffu, suma, 1);
        suma += __shfl_xor_sync(0xffffffffu, suma, 2);
        sumb += __shfl_xor_sync(0xffffffffu, sumb, 1);
        sumb += __shfl_xor_sync(0xffffffffu, sumb, 2);
        const float coef0 = __fdividef(__ldg(asrow + nb), suma);
        const float coef1 = __fdividef(__ldg(asrow + 8 * NBLK + nb), sumb);
        const ull c20 = pack2(coef0, coef0);
        const ull c21 = pack2(coef1, coef1);

        // ---- GEMM2 (W in registers): out += W @ V; attn_w written en route ----
        float* awp = awbase + nb * NTOK;
#pragma unroll
        for (int kt = 0; kt < 8; kt++) {
            uint32_t Awh[4], Awl[4];
#pragma unroll
            for (int half = 0; half < 2; half++) {
                int ni = 2 * kt + half;
                ull w0 = mul2(pack2(acc[ni][0], acc[ni][1]), c20);  // row g
                ull w1 = mul2(pack2(acc[ni][2], acc[ni][3]), c21);  // row g+8
                if (write_attn) {
                    *(ull*)(awp + ni * 8) = w0;
                    *(ull*)(awp + 8 * (NBLK * NTOK) + ni * 8) = w1;
                }
                float x0, x1, y0, y1;
                unpack2(w0, x0, x1);
                unpack2(w1, y0, y1);
                uint32_t hb0, hb1;
                asm("cvt.rn.bf16x2.f32 %0, %1, %2;" : "=r"(hb0) : "f"(x1), "f"(x0));
                asm("cvt.rn.bf16x2.f32 %0, %1, %2;" : "=r"(hb1) : "f"(y1), "f"(y0));
                Awh[half * 2] = hb0;
                Awh[half * 2 + 1] = hb1;
                ull hf0 = pack2(__int_as_float(hb0 << 16), __int_as_float(hb0 & 0xffff0000u));
                ull hf1 = pack2(__int_as_float(hb1 << 16), __int_as_float(hb1 & 0xffff0000u));
                ull l0v = fma2(hf0, NEG1_2, w0);
                ull l1v = fma2(hf1, NEG1_2, w1);
                float q0, q1, q2, q3;
                unpack2(l0v, q0, q1);
                unpack2(l1v, q2, q3);
                uint32_t lb0, lb1;
                asm("cvt.rn.bf16x2.f32 %0, %1, %2;" : "=r"(lb0) : "f"(q1), "f"(q0));
                asm("cvt.rn.bf16x2.f32 %0, %1, %2;" : "=r"(lb1) : "f"(q3), "f"(q2));
                Awl[half * 2] = lb0;
                Awl[half * 2 + 1] = lb1;
            }
#pragma unroll
            for (int np = 0; np < 4; np++) {
                uint32_t vh[4], vl[4];
                ldsm4t(vh, bV + kt * (16 * RB) + np * 32);
                ldsm4t(vl, bV + (OFF_VL - OFF_VH) + kt * (16 * RB) + np * 32);
                mma16816(acc2[2 * np], Awh, vh);
                mma16816(acc2[2 * np], Awh, vl);
                mma16816(acc2[2 * np], Awl, vh);
                mma16816(acc2[2 * np + 1], Awh, vh + 2);
                mma16816(acc2[2 * np + 1], Awh, vl + 2);
                mma16816(acc2[2 * np + 1], Awl, vh + 2);
            }
        }
    }

    // ---- store out (warp-private rows, no reduction) ----
#pragma unroll
    for (int h2 = 0; h2 < 2; h2++) {
        int row = wid * 16 + g + 8 * h2;
        float* op = out + (size_t)(b * LQ + l0 + row) * (HH * DH) + hd * DH + 2 * qd;
#pragma unroll
        for (int ni = 0; ni < 8; ni++) {
            float2 pv;
            pv.x = acc2[ni][2 * h2];
            pv.y = acc2[ni][2 * h2 + 1];
            *(float2*)(op + ni * 8) = pv;
        }
    }
}

extern "C" void kernel_launch(void* const* d_in, const int* in_sizes, int n_in,
                              void* d_out, int out_size) {
    (void)in_sizes; (void)n_in;
    const float* q = (const float*)d_in[0];
    const float* k = (const float*)d_in[1];
    const float* v = (const float*)d_in[2];
    const float* a = (const float*)d_in[3];
    float* out = (float*)d_out;

    int write_attn = ((size_t)out_size >= OUT_ELEMS + ATTN_ELEMS) ? 1 : 0;
    float* attnw = out + OUT_ELEMS;

    cudaFuncSetAttribute(attn_mma_kernel,
                         cudaFuncAttributeMaxDynamicSharedMemorySize, SMEM_BYTES);

    dim3 grid(BB * HH * (LQ / MT));  // 256
    attn_mma_kernel<<<grid, THREADS, SMEM_BYTES>>>(q, k, v, a, out, attnw, write_attn);
}

// round 12
// speedup vs baseline: 1.1680x; 1.1680x over previous
#include <cuda_runtime.h>
#include <cuda_bf16.h>
#include <cstdint>

#define BB 4
#define HH 8
#define LQ 512
#define NBLK 32
#define NTOK 128
#define DH 64
#define MT 128
#define THREADS 256

#define OUT_ELEMS  (BB * LQ * HH * DH)
#define ATTN_ELEMS ((size_t)BB * HH * LQ * NBLK * NTOK)

#define QSTR 72          // bf16 elements per row (64 + 8 pad)
#define RB (QSTR * 2)    // 144 bytes per row
#define TILE (128 * RB)  // 18432 bytes per 128-row tile
#define TBUF (4 * TILE)  // KH,KL,VH,VL

// smem byte offsets
#define OFF_QH 0
#define OFF_QL (OFF_QH + TILE)
#define OFF_T0 (OFF_QL + TILE)          // buffer 0: KH,KL,VH,VL
#define OFF_T1 (OFF_T0 + TBUF)          // buffer 1
#define OFF_RS (OFF_T1 + TBUF)          // 128*2 f32 rowsums
#define SMEM_BYTES (OFF_RS + 1024)      // 185344

#define RED_STR 66

typedef unsigned long long ull;

__device__ __forceinline__ uint32_t s2u(const void* p) {
    uint32_t a;
    asm("{ .reg .u64 t; cvta.to.shared.u64 t, %1; cvt.u32.u64 %0, t; }" : "=r"(a) : "l"(p));
    return a;
}
__device__ __forceinline__ ull pack2(float x, float y) {
    ull r; asm("mov.b64 %0, {%1,%2};" : "=l"(r) : "f"(x), "f"(y)); return r;
}
__device__ __forceinline__ void unpack2(ull v, float& x, float& y) {
    asm("mov.b64 {%0,%1}, %2;" : "=f"(x), "=f"(y) : "l"(v));
}
__device__ __forceinline__ ull add2(ull a, ull b) {
    ull d; asm("add.rn.f32x2 %0, %1, %2;" : "=l"(d) : "l"(a), "l"(b)); return d;
}
__device__ __forceinline__ ull mul2(ull a, ull b) {
    ull d; asm("mul.rn.f32x2 %0, %1, %2;" : "=l"(d) : "l"(a), "l"(b)); return d;
}
__device__ __forceinline__ ull fma2(ull a, ull b, ull c) {
    ull d; asm("fma.rn.f32x2 %0, %1, %2, %3;" : "=l"(d) : "l"(a), "l"(b), "l"(c)); return d;
}
__device__ __forceinline__ void ldsm4(uint32_t* r, uint32_t a) {
    asm volatile("ldmatrix.sync.aligned.m8n8.x4.shared.b16 {%0,%1,%2,%3}, [%4];"
                 : "=r"(r[0]), "=r"(r[1]), "=r"(r[2]), "=r"(r[3]) : "r"(a));
}
__device__ __forceinline__ void ldsm4t(uint32_t* r, uint32_t a) {
    asm volatile("ldmatrix.sync.aligned.m8n8.x4.trans.shared.b16 {%0,%1,%2,%3}, [%4];"
                 : "=r"(r[0]), "=r"(r[1]), "=r"(r[2]), "=r"(r[3]) : "r"(a));
}
__device__ __forceinline__ void mma16816(float* c, const uint32_t* a, const uint32_t* b) {
    asm volatile(
        "mma.sync.aligned.m16n8k16.row.col.f32.bf16.bf16.f32 "
        "{%0,%1,%2,%3}, {%4,%5,%6,%7}, {%8,%9}, {%0,%1,%2,%3};"
        : "+f"(c[0]), "+f"(c[1]), "+f"(c[2]), "+f"(c[3])
        : "r"(a[0]), "r"(a[1]), "r"(a[2]), "r"(a[3]), "r"(b[0]), "r"(b[1]));
}
__device__ __forceinline__ void barpair(int id) {
    asm volatile("bar.sync %0, 64;" :: "r"(id) : "memory");
}

// split one fp32 float4 into bf16 hi/lo, store 8B each
__device__ __forceinline__ void split_store(float4 v, char* base_hi, char* base_lo) {
    __nv_bfloat162 h0 = __floats2bfloat162_rn(v.x, v.y);
    __nv_bfloat162 h1 = __floats2bfloat162_rn(v.z, v.w);
    float lx = v.x - __bfloat162float(h0.x);
    float ly = v.y - __bfloat162float(h0.y);
    float lz = v.z - __bfloat162float(h1.x);
    float lw = v.w - __bfloat162float(h1.y);
    __nv_bfloat162 e0 = __floats2bfloat162_rn(lx, ly);
    __nv_bfloat162 e1 = __floats2bfloat162_rn(lz, lw);
    uint2 hh; hh.x = *(uint32_t*)&h0; hh.y = *(uint32_t*)&h1;
    uint2 ll; ll.x = *(uint32_t*)&e0; ll.y = *(uint32_t*)&e1;
    *(uint2*)base_hi = hh;
    *(uint2*)base_lo = ll;
}

__global__ __launch_bounds__(THREADS, 1)
void attn_mma_kernel(const float* __restrict__ qg, const float* __restrict__ kg,
                     const float* __restrict__ vg, const float* __restrict__ ag,
                     float* __restrict__ out, float* __restrict__ attnw, int write_attn) {
    extern __shared__ __align__(16) char sm[];
    const uint32_t sb = s2u(sm);
    const int tid = threadIdx.x, lane = tid & 31, wid = tid >> 5;
    const int wm = wid >> 1, wn = wid & 1;
    const int g = lane >> 2, qd = lane & 3;
    const int bx = blockIdx.x;
    const int qt = bx & 3, hd = (bx >> 2) & 7, b = bx >> 5;
    const int l0 = qt * MT;

    const size_t kvstride = (size_t)HH * NTOK * DH;
    const size_t kvoff0 = ((size_t)(b * NBLK) * HH + hd) * (NTOK * DH);
    const float4* kg4b = (const float4*)(kg + kvoff0);
    const float4* vg4b = (const float4*)(vg + kvoff0);

    // thread's split-store target (row/col fixed by tid)
    const int srow = (tid * 4) >> 6;          // idx>>4 with idx = tid + i*256: rows stride 16
    // actually recompute per i below (idx-dependent)

    // ---- Q load + split (scale = 1/8 * log2e folded) ----
    {
        const float SC = 0.125f * 1.4426950408889634f;
        const float4* qg4 = (const float4*)(qg + (size_t)((b * HH + hd) * LQ + l0) * DH);
#pragma unroll
        for (int i = 0; i < 8; i++) {
            int idx = tid + i * THREADS;
            int row = idx >> 4, c4 = idx & 15;
            float4 v = qg4[idx];
            v.x *= SC; v.y *= SC; v.z *= SC; v.w *= SC;
            char* base = sm + row * RB + c4 * 8;
            split_store(v, base + OFF_QH, base + OFF_QL);
        }
    }
    // ---- initial K/V block 0 split into buffer 0 ----
    {
#pragma unroll
        for (int i = 0; i < 8; i++) {
            int idx = tid + i * THREADS;
            int row = idx >> 4, c4 = idx & 15;
            char* base = sm + OFF_T0 + row * RB + c4 * 8;
            split_store(kg4b[idx], base, base + TILE);
            split_store(vg4b[idx], base + 2 * TILE, base + 3 * TILE);
        }
    }
    __syncthreads();

    // ldmatrix lane-offsets (byte offsets within tile)
    const uint32_t aQ = sb + OFF_QH +
        (uint32_t)((wm * 32 + (lane & 15)) * RB + (lane >> 4) * 16);
    const uint32_t bKoff = (uint32_t)((wn * 64 + ((lane >> 4) & 1) * 8 + (lane & 7)) * RB +
                                      ((lane >> 3) & 1) * 16);
    const uint32_t bVoff = (uint32_t)((wn * 64 + (lane & 15)) * RB + ((lane >> 4) & 1) * 16);

    float* rs = (float*)(sm + OFF_RS);
    const float* asbase = ag + (size_t)((b * HH + hd) * LQ + l0 + wm * 32 + g) * NBLK;
    float* awbase = attnw + (size_t)((b * HH + hd) * LQ + l0 + wm * 32 + g) * (NBLK * NTOK)
                    + wn * 64 + 2 * qd;

    float acc2[2][8][4];
#pragma unroll
    for (int mi = 0; mi < 2; mi++)
#pragma unroll
        for (int ni = 0; ni < 8; ni++)
#pragma unroll
            for (int j = 0; j < 4; j++) acc2[mi][ni][j] = 0.f;

    // exp2 constants
    const ull MAGIC2 = 0x4B4000004B400000ULL;
    const ull NMAGIC2 = 0xCB400000CB400000ULL;
    const ull NEG1_2 = 0xBF800000BF800000ULL;
    const ull ONE2 = 0x3F8000003F800000ULL;
    const ull C5 = pack2(0.0013333558f, 0.0013333558f);
    const ull C4 = pack2(0.0096181291f, 0.0096181291f);
    const ull C3 = pack2(0.0555041087f, 0.0555041087f);
    const ull C2 = pack2(0.2402265070f, 0.2402265070f);
    const ull C1 = pack2(0.6931471806f, 0.6931471806f);

    for (int nb = 0; nb < NBLK; nb++) {
        const int p = nb & 1;
        const uint32_t tb = (p ? OFF_T1 : OFF_T0);       // current tiles
        char* tnext = sm + (p ? OFF_T0 : OFF_T1);        // next tiles
        const uint32_t bKc = sb + tb + bKoff;
        const uint32_t bVc = sb + tb + 2 * TILE + bVoff;
        const bool more = (nb + 1 < NBLK);

        float acc[2][8][4];
#pragma unroll
        for (int mi = 0; mi < 2; mi++)
#pragma unroll
            for (int ni = 0; ni < 8; ni++)
#pragma unroll
                for (int j = 0; j < 4; j++) acc[mi][ni][j] = 0.f;

        // ---- issue K(nb+1) loads (latency hides under GEMM1 ks 0-1) ----
        float4 kb[8];
        if (more) {
            const float4* kp = kg4b + (size_t)(nb + 1) * (kvstride / 4);
#pragma unroll
            for (int j = 0; j < 8; j++) kb[j] = kp[tid + j * THREADS];
        }

#pragma unroll
        for (int ks = 0; ks < 2; ks++) {
            uint32_t Ah[2][4], Al[2][4];
#pragma unroll
            for (int mi = 0; mi < 2; mi++) {
                ldsm4(Ah[mi], aQ + mi * (16 * RB) + ks * 32);
                ldsm4(Al[mi], aQ + TILE + mi * (16 * RB) + ks * 32);
            }
#pragma unroll
            for (int np = 0; np < 4; np++) {
                uint32_t bh[4], bl[4];
                ldsm4(bh, bKc + np * (16 * RB) + ks * 32);
                ldsm4(bl, bKc + TILE + np * (16 * RB) + ks * 32);
#pragma unroll
                for (int mi = 0; mi < 2; mi++) {
                    mma16816(acc[mi][2 * np], Ah[mi], bh);
                    mma16816(acc[mi][2 * np], Ah[mi], bl);
                    mma16816(acc[mi][2 * np], Al[mi], bh);
                    mma16816(acc[mi][2 * np + 1], Ah[mi], bh + 2);
                    mma16816(acc[mi][2 * np + 1], Ah[mi], bl + 2);
                    mma16816(acc[mi][2 * np + 1], Al[mi], bh + 2);
                }
            }
        }

        // ---- store K split; issue V(nb+1) loads ----
        float4 vb[8];
        if (more) {
#pragma unroll
            for (int j = 0; j < 8; j++) {
                int idx = tid + j * THREADS;
                int row = idx >> 4, c4 = idx & 15;
                char* base = tnext + row * RB + c4 * 8;
                split_store(kb[j], base, base + TILE);
            }
            const float4* vp = vg4b + (size_t)(nb + 1) * (kvstride / 4);
#pragma unroll
            for (int j = 0; j < 8; j++) vb[j] = vp[tid + j * THREADS];
        }

#pragma unroll
        for (int ks = 2; ks < 4; ks++) {
            uint32_t Ah[2][4], Al[2][4];
#pragma unroll
            for (int mi = 0; mi < 2; mi++) {
                ldsm4(Ah[mi], aQ + mi * (16 * RB) + ks * 32);
                ldsm4(Al[mi], aQ + TILE + mi * (16 * RB) + ks * 32);
            }
#pragma unroll
            for (int np = 0; np < 4; np++) {
                uint32_t bh[4], bl[4];
                ldsm4(bh, bKc + np * (16 * RB) + ks * 32);
                ldsm4(bl, bKc + TILE + np * (16 * RB) + ks * 32);
#pragma unroll
                for (int mi = 0; mi < 2; mi++) {
                    mma16816(acc[mi][2 * np], Ah[mi], bh);
                    mma16816(acc[mi][2 * np], Ah[mi], bl);
                    mma16816(acc[mi][2 * np], Al[mi], bh);
                    mma16816(acc[mi][2 * np + 1], Ah[mi], bh + 2);
                    mma16816(acc[mi][2 * np + 1], Ah[mi], bl + 2);
                    mma16816(acc[mi][2 * np + 1], Al[mi], bh + 2);
                }
            }
        }

        // ---- store V split ----
        if (more) {
#pragma unroll
            for (int j = 0; j < 8; j++) {
                int idx = tid + j * THREADS;
                int row = idx >> 4, c4 = idx & 15;
                char* base = tnext + row * RB + c4 * 8;
                split_store(vb[j], base + 2 * TILE, base + 3 * TILE);
            }
        }

        // ---- softmax: e = 2^S, partial rowsums over this warp's t64 ----
        float coef[2][2];
#pragma unroll
        for (int mi = 0; mi < 2; mi++)
#pragma unroll
            for (int h2 = 0; h2 < 2; h2++) {
                ull s2 = 0ULL;
#pragma unroll
                for (int ni = 0; ni < 8; ni++) {
                    ull y2 = pack2(acc[mi][ni][2 * h2], acc[mi][ni][2 * h2 + 1]);
                    ull t2 = add2(y2, MAGIC2);
                    ull u2 = add2(t2, NMAGIC2);
                    ull f2 = fma2(u2, NEG1_2, y2);
                    ull p2 = fma2(C5, f2, C4);
                    p2 = fma2(p2, f2, C3);
                    p2 = fma2(p2, f2, C2);
                    p2 = fma2(p2, f2, C1);
                    p2 = fma2(p2, f2, ONE2);
                    uint32_t tlo = (uint32_t)t2, thi = (uint32_t)(t2 >> 32);
                    uint32_t plo = (uint32_t)p2, phi = (uint32_t)(p2 >> 32);
                    float e0 = __int_as_float(plo + (tlo << 23));
                    float e1 = __int_as_float(phi + (thi << 23));
                    acc[mi][ni][2 * h2] = e0;
                    acc[mi][ni][2 * h2 + 1] = e1;
                    s2 = add2(s2, pack2(e0, e1));
                }
                float slo, shi;
                unpack2(s2, slo, shi);
                float s = slo + shi;
                s += __shfl_xor_sync(0xffffffffu, s, 1);
                s += __shfl_xor_sync(0xffffffffu, s, 2);
                if (qd == 0) rs[(wm * 32 + mi * 16 + g + 8 * h2) * 2 + wn] = s;
            }
        barpair(1 + wm);
#pragma unroll
        for (int mi = 0; mi < 2; mi++)
#pragma unroll
            for (int h2 = 0; h2 < 2; h2++) {
                int r = wm * 32 + mi * 16 + g + 8 * h2;
                float tot = rs[r * 2] + rs[r * 2 + 1];
                coef[mi][h2] = __fdividef(__ldg(asbase + (mi * 16 + 8 * h2) * NBLK + nb), tot);
            }

        // ---- GEMM2 (W in registers): out += W @ V; attn_w written en route ----
        float* awp = awbase + nb * NTOK;
#pragma unroll
        for (int kt = 0; kt < 4; kt++) {
            uint32_t Awh[2][4], Awl[2][4];
#pragma unroll
            for (int mi = 0; mi < 2; mi++) {
                ull c2h0 = pack2(coef[mi][0], coef[mi][0]);
                ull c2h1 = pack2(coef[mi][1], coef[mi][1]);
#pragma unroll
                for (int half = 0; half < 2; half++) {
                    int ni = 2 * kt + half;
                    ull w0 = mul2(pack2(acc[mi][ni][0], acc[mi][ni][1]), c2h0);
                    ull w1 = mul2(pack2(acc[mi][ni][2], acc[mi][ni][3]), c2h1);
                    if (write_attn) {
                        *(ull*)(awp + (mi * 16) * (NBLK * NTOK) + ni * 8) = w0;
                        *(ull*)(awp + (mi * 16 + 8) * (NBLK * NTOK) + ni * 8) = w1;
                    }
                    float x0, x1, y0, y1;
                    unpack2(w0, x0, x1);
                    unpack2(w1, y0, y1);
                    uint32_t hb0, hb1;
                    asm("cvt.rn.bf16x2.f32 %0, %1, %2;" : "=r"(hb0) : "f"(x1), "f"(x0));
                    asm("cvt.rn.bf16x2.f32 %0, %1, %2;" : "=r"(hb1) : "f"(y1), "f"(y0));
                    Awh[mi][half * 2] = hb0;
                    Awh[mi][half * 2 + 1] = hb1;
                    ull hf0 = pack2(__int_as_float(hb0 << 16), __int_as_float(hb0 & 0xffff0000u));
                    ull hf1 = pack2(__int_as_float(hb1 << 16), __int_as_float(hb1 & 0xffff0000u));
                    ull l0v = fma2(hf0, NEG1_2, w0);
                    ull l1v = fma2(hf1, NEG1_2, w1);
                    float q0, q1, q2, q3;
                    unpack2(l0v, q0, q1);
                    unpack2(l1v, q2, q3);
                    uint32_t lb0, lb1;
                    asm("cvt.rn.bf16x2.f32 %0, %1, %2;" : "=r"(lb0) : "f"(q1), "f"(q0));
                    asm("cvt.rn.bf16x2.f32 %0, %1, %2;" : "=r"(lb1) : "f"(q3), "f"(q2));
                    Awl[mi][half * 2] = lb0;
                    Awl[mi][half * 2 + 1] = lb1;
                }
            }
#pragma unroll
            for (int np = 0; np < 4; np++) {
                uint32_t vh[4], vl[4];
                ldsm4t(vh, bVc + kt * (16 * RB) + np * 32);
                ldsm4t(vl, bVc + TILE + kt * (16 * RB) + np * 32);
#pragma unroll
                for (int mi = 0; mi < 2; mi++) {
                    mma16816(acc2[mi][2 * np], Awh[mi], vh);
                    mma16816(acc2[mi][2 * np], Awh[mi], vl);
                    mma16816(acc2[mi][2 * np], Awl[mi], vh);
                    mma16816(acc2[mi][2 * np + 1], Awh[mi], vh + 2);
                    mma16816(acc2[mi][2 * np + 1], Awh[mi], vl + 2);
                    mma16816(acc2[mi][2 * np + 1], Awl[mi], vh + 2);
                }
            }
        }
        __syncthreads();  // buf[1-p] complete; GEMM2(nb) done before next overwrite
    }

    // ---- pair reduction (wn=0 + wn=1) via T0 scratch, then store out ----
    float* red = (float*)(sm + OFF_T0) + wm * (32 * RED_STR);
    if (wn == 1) {
#pragma unroll
        for (int mi = 0; mi < 2; mi++)
#pragma unroll
            for (int h2 = 0; h2 < 2; h2++)
#pragma unroll
                for (int ni = 0; ni < 8; ni++) {
                    int row = mi * 16 + g + 8 * h2;
                    float2 pv;
                    pv.x = acc2[mi][ni][2 * h2];
                    pv.y = acc2[mi][ni][2 * h2 + 1];
                    *(float2*)(red + row * RED_STR + ni * 8 + 2 * qd) = pv;
                }
    }
    barpair(1 + wm);
    if (wn == 0) {
#pragma unroll
        for (int mi = 0; mi < 2; mi++)
#pragma unroll
            for (int h2 = 0; h2 < 2; h2++) {
                int row = mi * 16 + g + 8 * h2;
                float* op = out + (size_t)(b * LQ + l0 + wm * 32 + row) * (HH * DH) + hd * DH;
#pragma unroll
                for (int ni = 0; ni < 8; ni++) {
                    float2 o = *(float2*)(red + row * RED_STR + ni * 8 + 2 * qd);
                    float2 pv;
                    pv.x = acc2[mi][ni][2 * h2] + o.x;
                    pv.y = acc2[mi][ni][2 * h2 + 1] + o.y;
                    *(float2*)(op + ni * 8 + 2 * qd) = pv;
                }
            }
    }
}

extern "C" void kernel_launch(void* const* d_in, const int* in_sizes, int n_in,
                              void* d_out, int out_size) {
    (void)in_sizes; (void)n_in;
    const float* q = (const float*)d_in[0];
    const float* k = (const float*)d_in[1];
    const float* v = (const float*)d_in[2];
    const float* a = (const float*)d_in[3];
    float* out = (float*)d_out;

    int write_attn = ((size_t)out_size >= OUT_ELEMS + ATTN_ELEMS) ? 1 : 0;
    float* attnw = out + OUT_ELEMS;

    cudaFuncSetAttribute(attn_mma_kernel,
                         cudaFuncAttributeMaxDynamicSharedMemorySize, SMEM_BYTES);

    dim3 grid(BB * HH * (LQ / MT));  // 128
    attn_mma_kernel<<<grid, THREADS, SMEM_BYTES>>>(q, k, v, a, out, attnw, write_attn);
}